// round 1
// baseline (speedup 1.0000x reference)
#include <cuda_runtime.h>
#include <math.h>

#define BATCH 32
#define SEQ   2048
#define DIM   1024

// Scratch (static __device__ — no allocation inside kernel_launch)
__device__ float g_q[BATCH * DIM];        // q' = dh@W^T + W_b + U_b
__device__ float g_scores[BATCH * SEQ];   // pre-softmax scores

// ---------------------------------------------------------------------------
// Kernel 1: q'[b,d] = W_b[d] + U_b[d] + sum_e dh[b,e] * W_w[d,e]
// One warp per output element (32768 warps total).
// ---------------------------------------------------------------------------
__global__ void qproj_kernel(const float* __restrict__ dh,
                             const float* __restrict__ Ww,
                             const float* __restrict__ Wb,
                             const float* __restrict__ Ub) {
    int warp = (blockIdx.x * blockDim.x + threadIdx.x) >> 5;
    int lane = threadIdx.x & 31;
    if (warp >= BATCH * DIM) return;
    int b = warp / DIM, d = warp % DIM;
    const float* x = dh + b * DIM;
    const float* w = Ww + (size_t)d * DIM;
    float s = 0.f;
    #pragma unroll 4
    for (int e = lane; e < DIM; e += 32) s += x[e] * w[e];
    #pragma unroll
    for (int o = 16; o; o >>= 1) s += __shfl_xor_sync(0xffffffffu, s, o);
    if (lane == 0) g_q[warp] = s + Wb[d] + Ub[d];
}

// ---------------------------------------------------------------------------
// Kernel 2 (dominant): fused  scores[b,l] = v_b + sum_d v[d]*tanh(q'[b,d] + enc[b,l,:]·U[d,:])
// SGEMM 128x128x8 tiling, 256 threads, 8x8 micro-tile per thread.
// Output tile is NOT stored: reduced through tanh*v into per-row score
// accumulators in shared memory, looping over 8 column chunks of 128.
// Block = (one batch b) x (128 rows of l). Grid (16, 32).
// ---------------------------------------------------------------------------
__global__ __launch_bounds__(256, 2)
void score_kernel(const float* __restrict__ enc,
                  const float* __restrict__ Uw,
                  const float* __restrict__ vw,
                  const float* __restrict__ vb) {
    __shared__ float As[8][128];      // enc tile, transposed [k][row]
    __shared__ float Bs[8][128];      // U   tile, transposed [k][col]
    __shared__ float v_sh[128];
    __shared__ float q_sh[128];
    __shared__ float score_sm[128];

    const int b   = blockIdx.y;
    const int r0  = b * SEQ + blockIdx.x * 128;   // first global row (b,l)
    const int tid = threadIdx.x;
    const int tx  = tid & 15, ty = tid >> 4;
    const int rowbase = ty * 8;                   // rows this thread owns
    const int colbase = tx * 8;                   // cols this thread owns

    if (tid < 128) score_sm[tid] = 0.f;

    const int lrow = tid >> 1;        // 0..127: which tile row this thread loads
    const int seg  = (tid & 1) * 4;   // 0 or 4: which float4 within the 8-wide k slab

    const float* Aptr = enc + (size_t)(r0 + lrow) * DIM + seg;

    float acc[8][8];

    for (int nc = 0; nc < 8; ++nc) {
        const int n0 = nc * 128;
        __syncthreads();  // previous epilogue finished reading v_sh/q_sh
        if (tid < 128) {
            v_sh[tid] = vw[n0 + tid];
            q_sh[tid] = g_q[b * DIM + n0 + tid];
        }
        #pragma unroll
        for (int i = 0; i < 8; i++)
            #pragma unroll
            for (int j = 0; j < 8; j++) acc[i][j] = 0.f;

        const float* Bptr = Uw + (size_t)(n0 + lrow) * DIM + seg;

        for (int k0 = 0; k0 < DIM; k0 += 8) {
            float4 av = *(const float4*)(Aptr + k0);
            float4 bv = *(const float4*)(Bptr + k0);
            __syncthreads();
            As[seg + 0][lrow] = av.x; As[seg + 1][lrow] = av.y;
            As[seg + 2][lrow] = av.z; As[seg + 3][lrow] = av.w;
            Bs[seg + 0][lrow] = bv.x; Bs[seg + 1][lrow] = bv.y;
            Bs[seg + 2][lrow] = bv.z; Bs[seg + 3][lrow] = bv.w;
            __syncthreads();
            #pragma unroll
            for (int kk = 0; kk < 8; kk++) {
                float4 a0 = *(const float4*)&As[kk][rowbase];
                float4 a1 = *(const float4*)&As[kk][rowbase + 4];
                float4 b0 = *(const float4*)&Bs[kk][colbase];
                float4 b1 = *(const float4*)&Bs[kk][colbase + 4];
                float ar[8] = {a0.x, a0.y, a0.z, a0.w, a1.x, a1.y, a1.z, a1.w};
                float br[8] = {b0.x, b0.y, b0.z, b0.w, b1.x, b1.y, b1.z, b1.w};
                #pragma unroll
                for (int i = 0; i < 8; i++)
                    #pragma unroll
                    for (int j = 0; j < 8; j++) acc[i][j] += ar[i] * br[j];
            }
        }
        // Fused epilogue: reduce this 128-wide column chunk through tanh * v
        #pragma unroll
        for (int i = 0; i < 8; i++) {
            float s = 0.f;
            #pragma unroll
            for (int j = 0; j < 8; j++)
                s += v_sh[colbase + j] * tanhf(q_sh[colbase + j] + acc[i][j]);
            atomicAdd(&score_sm[rowbase + i], s);
        }
    }
    __syncthreads();
    if (tid < 128) g_scores[r0 + tid] = score_sm[tid] + vb[0];
}

// ---------------------------------------------------------------------------
// Kernel 3: softmax over L per batch. Writes attn into out[BATCH*DIM ...].
// ---------------------------------------------------------------------------
__global__ void softmax_kernel(float* __restrict__ out) {
    __shared__ float sm[SEQ];
    __shared__ float red[256];
    const int b = blockIdx.x, tid = threadIdx.x;

    float m = -1e30f;
    for (int l = tid; l < SEQ; l += 256) {
        float s = g_scores[b * SEQ + l];
        sm[l] = s;
        m = fmaxf(m, s);
    }
    red[tid] = m;
    __syncthreads();
    for (int o = 128; o; o >>= 1) {
        if (tid < o) red[tid] = fmaxf(red[tid], red[tid + o]);
        __syncthreads();
    }
    m = red[0];
    __syncthreads();

    float sum = 0.f;
    for (int l = tid; l < SEQ; l += 256) {
        float e = __expf(sm[l] - m);
        sm[l] = e;
        sum += e;
    }
    red[tid] = sum;
    __syncthreads();
    for (int o = 128; o; o >>= 1) {
        if (tid < o) red[tid] += red[tid + o];
        __syncthreads();
    }
    const float inv = 1.f / red[0];

    float* attn = out + BATCH * DIM;   // layout: [context | attn]
    for (int l = tid; l < SEQ; l += 256) attn[b * SEQ + l] = sm[l] * inv;
}

// ---------------------------------------------------------------------------
// Kernel 4: context[b,d] = sum_l attn[b,l] * enc[b,l,d]
// One block per batch, 256 threads x float4 (covers D=1024).
// ---------------------------------------------------------------------------
__global__ void context_kernel(const float* __restrict__ enc,
                               float* __restrict__ out) {
    __shared__ float attn_sm[SEQ];
    const int b = blockIdx.x, tid = threadIdx.x;
    const float* attn = out + BATCH * DIM + b * SEQ;
    for (int l = tid; l < SEQ; l += 256) attn_sm[l] = attn[l];
    __syncthreads();

    float4 acc = make_float4(0.f, 0.f, 0.f, 0.f);
    const float4* ep = (const float4*)(enc + (size_t)b * SEQ * DIM) + tid;
    #pragma unroll 4
    for (int l = 0; l < SEQ; ++l) {
        float a = attn_sm[l];
        float4 v = ep[(size_t)l * (DIM / 4)];
        acc.x += a * v.x; acc.y += a * v.y;
        acc.z += a * v.z; acc.w += a * v.w;
    }
    ((float4*)out)[b * (DIM / 4) + tid] = acc;
}

// ---------------------------------------------------------------------------
extern "C" void kernel_launch(void* const* d_in, const int* in_sizes, int n_in,
                              void* d_out, int out_size) {
    const float* dh  = (const float*)d_in[0];   // [32,1,1024]
    const float* enc = (const float*)d_in[1];   // [32,2048,1024]
    const float* Ww  = (const float*)d_in[2];   // [1024,1024]
    const float* Wb  = (const float*)d_in[3];   // [1024]
    const float* Uw  = (const float*)d_in[4];   // [1024,1024]
    const float* Ub  = (const float*)d_in[5];   // [1024]
    const float* vw  = (const float*)d_in[6];   // [1,1024]
    const float* vb  = (const float*)d_in[7];   // [1]
    float* out = (float*)d_out;                 // [32768 context | 65536 attn]

    (void)in_sizes; (void)n_in; (void)out_size;

    qproj_kernel<<<(BATCH * DIM * 32 + 255) / 256, 256>>>(dh, Ww, Wb, Ub);

    dim3 sgrid(SEQ / 128, BATCH);
    score_kernel<<<sgrid, 256>>>(enc, Uw, vw, vb);

    softmax_kernel<<<BATCH, 256>>>(out);
    context_kernel<<<BATCH, 256>>>(enc, out);
}

// round 2
// speedup vs baseline: 2.6899x; 2.6899x over previous
#include <cuda_runtime.h>
#include <math.h>
#include <stdint.h>

#define BATCH 32
#define SEQ   2048
#define DIM   1024

// Scratch (static __device__ — no allocation inside kernel_launch)
__device__ float g_q[BATCH * DIM];        // q' = dh@W^T + W_b + U_b
__device__ float g_scores[BATCH * SEQ];   // pre-softmax scores

__device__ __forceinline__ uint32_t f2tf(float x) {
    uint32_t r;
    asm("cvt.rna.tf32.f32 %0, %1;" : "=r"(r) : "f"(x));
    return r;
}

__device__ __forceinline__ void mma_tf32(float c[4], const uint32_t a[4], const uint32_t b[2]) {
    asm volatile(
        "mma.sync.aligned.m16n8k8.row.col.f32.tf32.tf32.f32 "
        "{%0,%1,%2,%3}, {%4,%5,%6,%7}, {%8,%9}, {%0,%1,%2,%3};"
        : "+f"(c[0]), "+f"(c[1]), "+f"(c[2]), "+f"(c[3])
        : "r"(a[0]), "r"(a[1]), "r"(a[2]), "r"(a[3]), "r"(b[0]), "r"(b[1]));
}

// ---------------------------------------------------------------------------
// Kernel 1: q'[b,d] = W_b[d] + U_b[d] + sum_e dh[b,e] * W_w[d,e]
// ---------------------------------------------------------------------------
__global__ void qproj_kernel(const float* __restrict__ dh,
                             const float* __restrict__ Ww,
                             const float* __restrict__ Wb,
                             const float* __restrict__ Ub) {
    int warp = (blockIdx.x * blockDim.x + threadIdx.x) >> 5;
    int lane = threadIdx.x & 31;
    if (warp >= BATCH * DIM) return;
    int b = warp / DIM, d = warp % DIM;
    const float* x = dh + b * DIM;
    const float* w = Ww + (size_t)d * DIM;
    float s = 0.f;
    #pragma unroll 4
    for (int e = lane; e < DIM; e += 32) s += x[e] * w[e];
    #pragma unroll
    for (int o = 16; o; o >>= 1) s += __shfl_xor_sync(0xffffffffu, s, o);
    if (lane == 0) g_q[warp] = s + Wb[d] + Ub[d];
}

// ---------------------------------------------------------------------------
// Kernel 2 (dominant): scores[b,l] = v_b + sum_d v[d]*tanh(q'[b,d] + enc[b,l,:]·U[d,:])
// tf32 mma.sync m16n8k8, block tile 128x128, K-chunk 32, 8 N-chunks fused
// through the tanh*v epilogue. Grid (SEQ/128, BATCH), 256 threads (8 warps:
// 2(M) x 4(N), warp tile 64x32 = 4x4 mma tiles).
// ---------------------------------------------------------------------------
__global__ __launch_bounds__(256)
void score_kernel(const float* __restrict__ enc,
                  const float* __restrict__ Uw,
                  const float* __restrict__ vw,
                  const float* __restrict__ vb) {
    // [k][m] / [k][n] transposed tiles, tf32 bits. Stride 136 => bank
    // pattern (k*8 + idx) mod 32 is conflict-free for the frag loads.
    __shared__ uint32_t As[32][136];
    __shared__ uint32_t Bs[32][136];
    __shared__ float v_sh[128];
    __shared__ float q_sh[128];
    __shared__ float score_sm[128];

    const int b    = blockIdx.y;
    const int l0   = blockIdx.x * 128;
    const int tid  = threadIdx.x;
    const int warp = tid >> 5;
    const int lane = tid & 31;
    const int mw   = warp >> 2;    // 0..1  -> M offset mw*64
    const int nw   = warp & 3;     // 0..3  -> N offset nw*32
    const int gr   = lane >> 2;    // 0..7
    const int gc   = lane & 3;     // 0..3

    if (tid < 128) score_sm[tid] = 0.f;

    // global -> smem mapping: 2 threads per row, 16 consecutive k each
    const int ldrow = tid >> 1;            // 0..127
    const int ldk   = (tid & 1) * 16;      // 0 or 16
    const float* Abase = enc + ((size_t)b * SEQ + l0 + ldrow) * DIM + ldk;

    float acc[4][4][4];

    for (int nc = 0; nc < 8; ++nc) {
        const int n0 = nc * 128;
        __syncthreads();   // epilogue of prev chunk done reading v_sh/q_sh
        if (tid < 128) {
            v_sh[tid] = vw[n0 + tid];
            q_sh[tid] = g_q[b * DIM + n0 + tid];
        }
        #pragma unroll
        for (int i = 0; i < 4; i++)
            #pragma unroll
            for (int j = 0; j < 4; j++)
                #pragma unroll
                for (int r = 0; r < 4; r++) acc[i][j][r] = 0.f;

        const float* Bbase = Uw + (size_t)(n0 + ldrow) * DIM + ldk;

        for (int k0 = 0; k0 < DIM; k0 += 32) {
            float4 a4[4], b4[4];
            #pragma unroll
            for (int j = 0; j < 4; j++) {
                a4[j] = *(const float4*)(Abase + k0 + j * 4);
                b4[j] = *(const float4*)(Bbase + k0 + j * 4);
            }
            __syncthreads();   // prior mma stage done reading As/Bs
            #pragma unroll
            for (int j = 0; j < 4; j++) {
                int kk = ldk + j * 4;
                As[kk + 0][ldrow] = f2tf(a4[j].x);
                As[kk + 1][ldrow] = f2tf(a4[j].y);
                As[kk + 2][ldrow] = f2tf(a4[j].z);
                As[kk + 3][ldrow] = f2tf(a4[j].w);
                Bs[kk + 0][ldrow] = f2tf(b4[j].x);
                Bs[kk + 1][ldrow] = f2tf(b4[j].y);
                Bs[kk + 2][ldrow] = f2tf(b4[j].z);
                Bs[kk + 3][ldrow] = f2tf(b4[j].w);
            }
            __syncthreads();

            #pragma unroll
            for (int ks = 0; ks < 4; ++ks) {
                const int kb = ks * 8;
                uint32_t af[4][4], bf[4][2];
                #pragma unroll
                for (int i = 0; i < 4; i++) {
                    int m = mw * 64 + i * 16 + gr;
                    af[i][0] = As[kb + gc][m];
                    af[i][1] = As[kb + gc][m + 8];
                    af[i][2] = As[kb + gc + 4][m];
                    af[i][3] = As[kb + gc + 4][m + 8];
                }
                #pragma unroll
                for (int j = 0; j < 4; j++) {
                    int n = nw * 32 + j * 8 + gr;
                    bf[j][0] = Bs[kb + gc][n];
                    bf[j][1] = Bs[kb + gc + 4][n];
                }
                #pragma unroll
                for (int i = 0; i < 4; i++)
                    #pragma unroll
                    for (int j = 0; j < 4; j++)
                        mma_tf32(acc[i][j], af[i], bf[j]);
            }
        }

        // Fused epilogue: reduce 128-wide d-chunk through tanh * v
        #pragma unroll
        for (int i = 0; i < 4; i++) {
            float slo = 0.f, shi = 0.f;
            #pragma unroll
            for (int j = 0; j < 4; j++) {
                int c = nw * 32 + j * 8 + gc * 2;
                float v0 = v_sh[c], v1 = v_sh[c + 1];
                float q0 = q_sh[c], q1 = q_sh[c + 1];
                slo += v0 * tanhf(q0 + acc[i][j][0]) + v1 * tanhf(q1 + acc[i][j][1]);
                shi += v0 * tanhf(q0 + acc[i][j][2]) + v1 * tanhf(q1 + acc[i][j][3]);
            }
            slo += __shfl_xor_sync(0xffffffffu, slo, 1);
            slo += __shfl_xor_sync(0xffffffffu, slo, 2);
            shi += __shfl_xor_sync(0xffffffffu, shi, 1);
            shi += __shfl_xor_sync(0xffffffffu, shi, 2);
            if (gc == 0) {
                int r = mw * 64 + i * 16 + gr;
                atomicAdd(&score_sm[r], slo);
                atomicAdd(&score_sm[r + 8], shi);
            }
        }
    }
    __syncthreads();
    if (tid < 128) g_scores[(size_t)b * SEQ + l0 + tid] = score_sm[tid] + vb[0];
}

// ---------------------------------------------------------------------------
// Kernel 3: softmax over L per batch; also zero-initializes the context
// region of out (context kernel atomically accumulates afterwards).
// ---------------------------------------------------------------------------
__global__ void softmax_kernel(float* __restrict__ out) {
    __shared__ float sm[SEQ];
    __shared__ float red[256];
    const int b = blockIdx.x, tid = threadIdx.x;

    for (int d = tid; d < DIM; d += 256) out[b * DIM + d] = 0.f;

    float m = -1e30f;
    for (int l = tid; l < SEQ; l += 256) {
        float s = g_scores[b * SEQ + l];
        sm[l] = s;
        m = fmaxf(m, s);
    }
    red[tid] = m;
    __syncthreads();
    for (int o = 128; o; o >>= 1) {
        if (tid < o) red[tid] = fmaxf(red[tid], red[tid + o]);
        __syncthreads();
    }
    m = red[0];
    __syncthreads();

    float sum = 0.f;
    for (int l = tid; l < SEQ; l += 256) {
        float e = __expf(sm[l] - m);
        sm[l] = e;
        sum += e;
    }
    red[tid] = sum;
    __syncthreads();
    for (int o = 128; o; o >>= 1) {
        if (tid < o) red[tid] += red[tid + o];
        __syncthreads();
    }
    const float inv = 1.f / red[0];

    float* attn = out + BATCH * DIM;
    for (int l = tid; l < SEQ; l += 256) attn[b * SEQ + l] = sm[l] * inv;
}

// ---------------------------------------------------------------------------
// Kernel 4: context[b,d] += sum_{l in chunk} attn[b,l] * enc[b,l,d]
// Grid (BATCH, 8): each block covers 256 rows of L, atomicAdd partials.
// ---------------------------------------------------------------------------
__global__ void context_kernel(const float* __restrict__ enc,
                               float* __restrict__ out) {
    __shared__ float attn_sm[256];
    const int b = blockIdx.x, ch = blockIdx.y, tid = threadIdx.x;
    const int lbase = ch * 256;
    attn_sm[tid] = out[BATCH * DIM + (size_t)b * SEQ + lbase + tid];
    __syncthreads();

    float4 acc = make_float4(0.f, 0.f, 0.f, 0.f);
    const float4* ep = (const float4*)(enc + ((size_t)b * SEQ + lbase) * DIM) + tid;
    #pragma unroll 8
    for (int l = 0; l < 256; ++l) {
        float a = attn_sm[l];
        float4 v = ep[(size_t)l * (DIM / 4)];
        acc.x += a * v.x; acc.y += a * v.y;
        acc.z += a * v.z; acc.w += a * v.w;
    }
    float* dst = out + b * DIM + tid * 4;
    atomicAdd(dst + 0, acc.x);
    atomicAdd(dst + 1, acc.y);
    atomicAdd(dst + 2, acc.z);
    atomicAdd(dst + 3, acc.w);
}

// ---------------------------------------------------------------------------
extern "C" void kernel_launch(void* const* d_in, const int* in_sizes, int n_in,
                              void* d_out, int out_size) {
    const float* dh  = (const float*)d_in[0];   // [32,1,1024]
    const float* enc = (const float*)d_in[1];   // [32,2048,1024]
    const float* Ww  = (const float*)d_in[2];   // [1024,1024]
    const float* Wb  = (const float*)d_in[3];   // [1024]
    const float* Uw  = (const float*)d_in[4];   // [1024,1024]
    const float* Ub  = (const float*)d_in[5];   // [1024]
    const float* vw  = (const float*)d_in[6];   // [1,1024]
    const float* vb  = (const float*)d_in[7];   // [1]
    float* out = (float*)d_out;                 // [32768 context | 65536 attn]

    (void)in_sizes; (void)n_in; (void)out_size;

    qproj_kernel<<<(BATCH * DIM * 32 + 255) / 256, 256>>>(dh, Ww, Wb, Ub);

    dim3 sgrid(SEQ / 128, BATCH);
    score_kernel<<<sgrid, 256>>>(enc, Uw, vw, vb);

    softmax_kernel<<<BATCH, 256>>>(out);

    dim3 cgrid(BATCH, 8);
    context_kernel<<<cgrid, 256>>>(enc, out);
}

// round 4
// speedup vs baseline: 4.2777x; 1.5903x over previous
#include <cuda_runtime.h>
#include <math.h>
#include <stdint.h>

#define BATCH 32
#define SEQ   2048
#define DIM   1024

#define BM 128
#define BN 256
#define BK 32
#define STAGES 3
#define NCHUNK (DIM / BK)          // 32
#define ROWSTRIDE 36               // floats per smem row (conflict-free)
#define A_FLOATS (BM * ROWSTRIDE)  // 4608
#define STAGE_FLOATS ((BM + BN) * ROWSTRIDE)   // 13824
#define SMEM_FLOATS (STAGES * STAGE_FLOATS + 2 * BN)
#define SMEM_BYTES  (SMEM_FLOATS * 4)

// Scratch (static __device__ — no allocation inside kernel_launch)
__device__ float g_q[BATCH * DIM];        // q' = dh@W^T + W_b + U_b
__device__ float g_scores[BATCH * SEQ];   // pre-softmax scores (atomic-accumulated)

__device__ __forceinline__ uint32_t smem_u32(const void* p) {
    uint32_t a;
    asm("{ .reg .u64 t; cvta.to.shared.u64 t, %1; cvt.u32.u64 %0, t; }"
        : "=r"(a) : "l"(p));
    return a;
}

__device__ __forceinline__ void cp16(uint32_t dst, const float* src) {
    asm volatile("cp.async.cg.shared.global [%0], [%1], 16;"
                 :: "r"(dst), "l"(src) : "memory");
}
#define CP_COMMIT() asm volatile("cp.async.commit_group;" ::: "memory")
#define CP_WAIT(n)  asm volatile("cp.async.wait_group %0;" :: "n"(n) : "memory")

__device__ __forceinline__ void mma_tf32(float c[4], const uint32_t a[4], const uint32_t b[2]) {
    asm volatile(
        "mma.sync.aligned.m16n8k8.row.col.f32.tf32.tf32.f32 "
        "{%0,%1,%2,%3}, {%4,%5,%6,%7}, {%8,%9}, {%0,%1,%2,%3};"
        : "+f"(c[0]), "+f"(c[1]), "+f"(c[2]), "+f"(c[3])
        : "r"(a[0]), "r"(a[1]), "r"(a[2]), "r"(a[3]), "r"(b[0]), "r"(b[1]));
}

// ---------------------------------------------------------------------------
// Kernel 1: q'[b,d] = W_b[d] + U_b[d] + sum_e dh[b,e] * W_w[d,e]
// Also zeroes g_scores (score kernel accumulates atomically).
// ---------------------------------------------------------------------------
__global__ void qproj_kernel(const float* __restrict__ dh,
                             const float* __restrict__ Ww,
                             const float* __restrict__ Wb,
                             const float* __restrict__ Ub) {
    int gid = blockIdx.x * blockDim.x + threadIdx.x;
    if (gid < BATCH * SEQ) g_scores[gid] = 0.f;

    int warp = gid >> 5;
    int lane = threadIdx.x & 31;
    if (warp >= BATCH * DIM) return;
    int b = warp / DIM, d = warp % DIM;
    const float* x = dh + b * DIM;
    const float* w = Ww + (size_t)d * DIM;
    float s = 0.f;
    #pragma unroll 4
    for (int e = lane; e < DIM; e += 32) s += x[e] * w[e];
    #pragma unroll
    for (int o = 16; o; o >>= 1) s += __shfl_xor_sync(0xffffffffu, s, o);
    if (lane == 0) g_q[warp] = s + Wb[d] + Ub[d];
}

// ---------------------------------------------------------------------------
// Kernel 2 (dominant): partial scores for a 128(l) x 256(d) tile, full K=1024.
//   scores[b,l] += sum_{n in tile} v[n] * tanh(q'[b,n] + enc[b,l,:]·U[n,:])
// tf32 mma.sync m16n8k8, cp.async 3-stage pipeline, raw-fp32-as-tf32 (no cvt).
// Grid (8 nchunks, 16 ltiles, 32 batch), 512 threads = 16 warps (4m x 4n),
// warp tile 32x64 (2x8 mma tiles, acc 64 regs).
// ---------------------------------------------------------------------------
__global__ __launch_bounds__(512, 1)
void score_kernel(const float* __restrict__ enc,
                  const float* __restrict__ Uw,
                  const float* __restrict__ vw) {
    extern __shared__ float smf[];
    const uint32_t sb = smem_u32(smf);

    const int tid  = threadIdx.x;
    const int wid  = tid >> 5;
    const int lane = tid & 31;
    const int wm   = wid & 3;          // warp m index (0..3) -> m offset wm*32
    const int wn   = wid >> 2;         // warp n index (0..3) -> n offset wn*64
    const int gr   = lane >> 2;        // 0..7
    const int gc   = lane & 3;         // 0..3

    const int n0 = blockIdx.x * BN;
    const int l0 = blockIdx.y * BM;
    const int b  = blockIdx.z;

    const float* Abase = enc + ((size_t)b * SEQ + l0) * DIM;
    const float* Bbase = Uw + (size_t)n0 * DIM;

    float* q_sh = smf + STAGES * STAGE_FLOATS;
    float* v_sh = q_sh + BN;
    if (tid < BN) {
        q_sh[tid] = g_q[b * DIM + n0 + tid];
        v_sh[tid] = vw[n0 + tid];
    }

    // per-thread cp.async source/dest mapping
    const int arow = tid >> 3;           // A: ops 0..1023 -> thread does 2 (rows tid/8, +64)
    const int aseg = (tid & 7) * 4;      // float offset within 32-wide row

    // prologue: fill all 3 stages
    #pragma unroll
    for (int s = 0; s < STAGES; s++) {
        const int kf = s * BK;           // k offset in floats
        uint32_t stb = sb + (s * STAGE_FLOATS) * 4;
        #pragma unroll
        for (int r = 0; r < 2; r++) {
            int row = arow + r * 64;
            cp16(stb + (row * ROWSTRIDE + aseg) * 4, Abase + (size_t)row * DIM + kf + aseg);
        }
        #pragma unroll
        for (int r = 0; r < 4; r++) {
            int row = arow + r * 64;
            cp16(stb + (A_FLOATS + row * ROWSTRIDE + aseg) * 4,
                 Bbase + (size_t)row * DIM + kf + aseg);
        }
        CP_COMMIT();
    }

    float acc[2][8][4];
    #pragma unroll
    for (int i = 0; i < 2; i++)
        #pragma unroll
        for (int j = 0; j < 8; j++)
            #pragma unroll
            for (int r = 0; r < 4; r++) acc[i][j][r] = 0.f;

    for (int kc = 0; kc < NCHUNK; kc++) {
        const int st = kc % STAGES;
        CP_WAIT(STAGES - 1);
        __syncthreads();

        const float* As = smf + st * STAGE_FLOATS;
        const float* Bs = As + A_FLOATS;

        #pragma unroll
        for (int ks = 0; ks < 4; ks++) {
            const int kb = ks * 8;
            uint32_t af[2][4], bf[8][2];
            #pragma unroll
            for (int i = 0; i < 2; i++) {
                const int m = wm * 32 + i * 16 + gr;
                af[i][0] = __float_as_uint(As[m * ROWSTRIDE + kb + gc]);
                af[i][1] = __float_as_uint(As[(m + 8) * ROWSTRIDE + kb + gc]);
                af[i][2] = __float_as_uint(As[m * ROWSTRIDE + kb + gc + 4]);
                af[i][3] = __float_as_uint(As[(m + 8) * ROWSTRIDE + kb + gc + 4]);
            }
            #pragma unroll
            for (int j = 0; j < 8; j++) {
                const int n = wn * 64 + j * 8 + gr;
                bf[j][0] = __float_as_uint(Bs[n * ROWSTRIDE + kb + gc]);
                bf[j][1] = __float_as_uint(Bs[n * ROWSTRIDE + kb + gc + 4]);
            }
            #pragma unroll
            for (int i = 0; i < 2; i++)
                #pragma unroll
                for (int j = 0; j < 8; j++)
                    mma_tf32(acc[i][j], af[i], bf[j]);
        }
        __syncthreads();

        // refill this stage with chunk kc+STAGES
        const int kn = kc + STAGES;
        if (kn < NCHUNK) {
            const int kf = kn * BK;
            uint32_t stb = sb + (st * STAGE_FLOATS) * 4;
            #pragma unroll
            for (int r = 0; r < 2; r++) {
                int row = arow + r * 64;
                cp16(stb + (row * ROWSTRIDE + aseg) * 4, Abase + (size_t)row * DIM + kf + aseg);
            }
            #pragma unroll
            for (int r = 0; r < 4; r++) {
                int row = arow + r * 64;
                cp16(stb + (A_FLOATS + row * ROWSTRIDE + aseg) * 4,
                     Bbase + (size_t)row * DIM + kf + aseg);
            }
        }
        CP_COMMIT();   // commit (possibly empty) group to keep wait counts aligned
    }

    // Fused epilogue: reduce the 256-wide d-chunk through tanh * v, then
    // atomic-accumulate per-row partials into g_scores.
    #pragma unroll
    for (int i = 0; i < 2; i++) {
        float slo = 0.f, shi = 0.f;
        #pragma unroll
        for (int j = 0; j < 8; j++) {
            const int c = wn * 64 + j * 8 + gc * 2;
            const float v0 = v_sh[c], v1 = v_sh[c + 1];
            const float q0 = q_sh[c], q1 = q_sh[c + 1];
            float x0 = q0 + acc[i][j][0], x1 = q1 + acc[i][j][1];
            float x2 = q0 + acc[i][j][2], x3 = q1 + acc[i][j][3];
            slo += v0 * (1.f - 2.f / (__expf(2.f * x0) + 1.f))
                 + v1 * (1.f - 2.f / (__expf(2.f * x1) + 1.f));
            shi += v0 * (1.f - 2.f / (__expf(2.f * x2) + 1.f))
                 + v1 * (1.f - 2.f / (__expf(2.f * x3) + 1.f));
        }
        slo += __shfl_xor_sync(0xffffffffu, slo, 1);
        slo += __shfl_xor_sync(0xffffffffu, slo, 2);
        shi += __shfl_xor_sync(0xffffffffu, shi, 1);
        shi += __shfl_xor_sync(0xffffffffu, shi, 2);
        if (gc == 0) {
            const int r = l0 + wm * 32 + i * 16 + gr;
            atomicAdd(&g_scores[(size_t)b * SEQ + r], slo);
            atomicAdd(&g_scores[(size_t)b * SEQ + r + 8], shi);
        }
    }
}

// ---------------------------------------------------------------------------
// Kernel 3: softmax over L per batch (softmax invariant to +v_b, so v_b is
// dropped entirely); zero-inits the context region of out.
// ---------------------------------------------------------------------------
__global__ void softmax_kernel(float* __restrict__ out) {
    __shared__ float sm[SEQ];
    __shared__ float red[256];
    const int b = blockIdx.x, tid = threadIdx.x;

    for (int d = tid; d < DIM; d += 256) out[b * DIM + d] = 0.f;

    float m = -1e30f;
    for (int l = tid; l < SEQ; l += 256) {
        float s = g_scores[b * SEQ + l];
        sm[l] = s;
        m = fmaxf(m, s);
    }
    red[tid] = m;
    __syncthreads();
    for (int o = 128; o; o >>= 1) {
        if (tid < o) red[tid] = fmaxf(red[tid], red[tid + o]);
        __syncthreads();
    }
    m = red[0];
    __syncthreads();

    float sum = 0.f;
    for (int l = tid; l < SEQ; l += 256) {
        float e = __expf(sm[l] - m);
        sm[l] = e;
        sum += e;
    }
    red[tid] = sum;
    __syncthreads();
    for (int o = 128; o; o >>= 1) {
        if (tid < o) red[tid] += red[tid + o];
        __syncthreads();
    }
    const float inv = 1.f / red[0];

    float* attn = out + BATCH * DIM;
    for (int l = tid; l < SEQ; l += 256) attn[b * SEQ + l] = sm[l] * inv;
}

// ---------------------------------------------------------------------------
// Kernel 4: context[b,d] += sum_{l in chunk} attn[b,l] * enc[b,l,d]
// Grid (BATCH, 16): 128 L-rows per block, atomicAdd fp32 partials.
// ---------------------------------------------------------------------------
__global__ void context_kernel(const float* __restrict__ enc,
                               float* __restrict__ out) {
    __shared__ float attn_sm[128];
    const int b = blockIdx.x, ch = blockIdx.y, tid = threadIdx.x;
    const int lbase = ch * 128;
    if (tid < 128) attn_sm[tid] = out[BATCH * DIM + (size_t)b * SEQ + lbase + tid];
    __syncthreads();

    float4 acc = make_float4(0.f, 0.f, 0.f, 0.f);
    const float4* ep = (const float4*)(enc + ((size_t)b * SEQ + lbase) * DIM) + tid;
    #pragma unroll 8
    for (int l = 0; l < 128; ++l) {
        float a = attn_sm[l];
        float4 v = ep[(size_t)l * (DIM / 4)];
        acc.x += a * v.x; acc.y += a * v.y;
        acc.z += a * v.z; acc.w += a * v.w;
    }
    float* dst = out + b * DIM + tid * 4;
    atomicAdd(dst + 0, acc.x);
    atomicAdd(dst + 1, acc.y);
    atomicAdd(dst + 2, acc.z);
    atomicAdd(dst + 3, acc.w);
}

// ---------------------------------------------------------------------------
extern "C" void kernel_launch(void* const* d_in, const int* in_sizes, int n_in,
                              void* d_out, int out_size) {
    const float* dh  = (const float*)d_in[0];   // [32,1,1024]
    const float* enc = (const float*)d_in[1];   // [32,2048,1024]
    const float* Ww  = (const float*)d_in[2];   // [1024,1024]
    const float* Wb  = (const float*)d_in[3];   // [1024]
    const float* Uw  = (const float*)d_in[4];   // [1024,1024]
    const float* Ub  = (const float*)d_in[5];   // [1024]
    const float* vw  = (const float*)d_in[6];   // [1,1024]
    float* out = (float*)d_out;                 // [32768 context | 65536 attn]

    (void)in_sizes; (void)n_in; (void)out_size;

    static bool attr_set = false;
    if (!attr_set) {
        cudaFuncSetAttribute(score_kernel,
                             cudaFuncAttributeMaxDynamicSharedMemorySize, SMEM_BYTES);
        attr_set = true;
    }

    qproj_kernel<<<(BATCH * DIM * 32 + 255) / 256, 256>>>(dh, Ww, Wb, Ub);

    dim3 sgrid(DIM / BN, SEQ / BM, BATCH);   // (8, 16, 32)
    score_kernel<<<sgrid, 512, SMEM_BYTES>>>(enc, Uw, vw);

    softmax_kernel<<<BATCH, 256>>>(out);

    dim3 cgrid(BATCH, 16);
    context_kernel<<<cgrid, 256>>>(enc, out);
}

// round 5
// speedup vs baseline: 7.1643x; 1.6748x over previous
#include <cuda_runtime.h>
#include <cuda_fp16.h>
#include <math.h>
#include <stdint.h>

#define BATCH 32
#define SEQ   2048
#define DIM   1024

#define BM 128
#define BN 256
#define BKH 64                      // k halfs per chunk (128 B)
#define STAGES 3
#define NCHUNK (DIM / BKH)          // 16
#define ROWH 72                     // halfs per smem row (144 B stride, LDSM conflict-free)
#define A_HALFS (BM * ROWH)         // 9216
#define STAGE_HALFS ((BM + BN) * ROWH)   // 27648
#define SMEM_BYTES (STAGES * STAGE_HALFS * 2 + 2 * BN * 4)

// Scratch (static __device__ — no allocation inside kernel_launch)
__device__ float  g_q[BATCH * DIM];
__device__ float  g_scores[BATCH * SEQ];
__device__ __half g_enc_h[(size_t)BATCH * SEQ * DIM];   // fp16 copy of enc
__device__ __half g_U_h[DIM * DIM];                     // fp16 copy of Uw

__device__ __forceinline__ uint32_t smem_u32(const void* p) {
    uint32_t a;
    asm("{ .reg .u64 t; cvta.to.shared.u64 t, %1; cvt.u32.u64 %0, t; }"
        : "=r"(a) : "l"(p));
    return a;
}

__device__ __forceinline__ void cp16(uint32_t dst, const void* src) {
    asm volatile("cp.async.cg.shared.global [%0], [%1], 16;"
                 :: "r"(dst), "l"(src) : "memory");
}
#define CP_COMMIT() asm volatile("cp.async.commit_group;" ::: "memory")
#define CP_WAIT(n)  asm volatile("cp.async.wait_group %0;" :: "n"(n) : "memory")

__device__ __forceinline__ void ldm_x4(uint32_t r[4], uint32_t addr) {
    asm volatile("ldmatrix.sync.aligned.m8n8.x4.shared.b16 {%0,%1,%2,%3}, [%4];"
                 : "=r"(r[0]), "=r"(r[1]), "=r"(r[2]), "=r"(r[3]) : "r"(addr));
}

__device__ __forceinline__ void mma_f16(float c[4], const uint32_t a[4], const uint32_t b[2]) {
    asm volatile(
        "mma.sync.aligned.m16n8k16.row.col.f32.f16.f16.f32 "
        "{%0,%1,%2,%3}, {%4,%5,%6,%7}, {%8,%9}, {%0,%1,%2,%3};"
        : "+f"(c[0]), "+f"(c[1]), "+f"(c[2]), "+f"(c[3])
        : "r"(a[0]), "r"(a[1]), "r"(a[2]), "r"(a[3]), "r"(b[0]), "r"(b[1]));
}

// ---------------------------------------------------------------------------
// Kernel 0: fp32 -> fp16 conversion of enc and Uw (one-shot, DRAM-bound).
// Each thread converts 8 elements (float4 x2 -> uint4 of 8 halfs).
// ---------------------------------------------------------------------------
__global__ void convert_kernel(const float* __restrict__ enc,
                               const float* __restrict__ Uw) {
    const size_t nEnc8 = (size_t)BATCH * SEQ * DIM / 8;
    const size_t nU8   = (size_t)DIM * DIM / 8;
    size_t i = (size_t)blockIdx.x * blockDim.x + threadIdx.x;
    const float4* src;
    uint4* dst;
    size_t k;
    if (i < nEnc8)           { src = (const float4*)enc; dst = (uint4*)g_enc_h; k = i; }
    else if (i < nEnc8 + nU8){ src = (const float4*)Uw;  dst = (uint4*)g_U_h;   k = i - nEnc8; }
    else return;
    float4 f0 = src[k * 2], f1 = src[k * 2 + 1];
    __half2 h[4];
    h[0] = __floats2half2_rn(f0.x, f0.y);
    h[1] = __floats2half2_rn(f0.z, f0.w);
    h[2] = __floats2half2_rn(f1.x, f1.y);
    h[3] = __floats2half2_rn(f1.z, f1.w);
    dst[k] = *(uint4*)h;
}

// ---------------------------------------------------------------------------
// Kernel 1: q'[b,d] = W_b[d] + U_b[d] + sum_e dh[b,e] * W_w[d,e]  (fp32)
// Also zeroes g_scores.
// ---------------------------------------------------------------------------
__global__ void qproj_kernel(const float* __restrict__ dh,
                             const float* __restrict__ Ww,
                             const float* __restrict__ Wb,
                             const float* __restrict__ Ub) {
    int gid = blockIdx.x * blockDim.x + threadIdx.x;
    if (gid < BATCH * SEQ) g_scores[gid] = 0.f;

    int warp = gid >> 5;
    int lane = threadIdx.x & 31;
    if (warp >= BATCH * DIM) return;
    int b = warp / DIM, d = warp % DIM;
    const float* x = dh + b * DIM;
    const float* w = Ww + (size_t)d * DIM;
    float s = 0.f;
    #pragma unroll 4
    for (int e = lane; e < DIM; e += 32) s += x[e] * w[e];
    #pragma unroll
    for (int o = 16; o; o >>= 1) s += __shfl_xor_sync(0xffffffffu, s, o);
    if (lane == 0) g_q[warp] = s + Wb[d] + Ub[d];
}

// ---------------------------------------------------------------------------
// Kernel 2 (dominant): fp16 mma m16n8k16, cp.async 3-stage, ldmatrix frags.
// Tile 128(l) x 256(d), full K=1024; fused tanh*v epilogue; atomic partials.
// Grid (8, 16, 32), 512 threads = 16 warps (4m x 4n), warp tile 32x64.
// ---------------------------------------------------------------------------
__global__ __launch_bounds__(512, 1)
void score_kernel(const float* __restrict__ vw) {
    extern __shared__ char smc[];
    __half* smh = (__half*)smc;
    const uint32_t sb = smem_u32(smh);

    const int tid  = threadIdx.x;
    const int wid  = tid >> 5;
    const int lane = tid & 31;
    const int wm   = wid & 3;
    const int wn   = wid >> 2;
    const int gr   = lane >> 2;
    const int gc   = lane & 3;

    const int n0 = blockIdx.x * BN;
    const int l0 = blockIdx.y * BM;
    const int b  = blockIdx.z;

    const __half* Abase = g_enc_h + ((size_t)b * SEQ + l0) * DIM;
    const __half* Bbase = g_U_h + (size_t)n0 * DIM;

    float* q_sh = (float*)(smc + STAGES * STAGE_HALFS * 2);
    float* v_sh = q_sh + BN;
    if (tid < BN) {
        q_sh[tid] = g_q[b * DIM + n0 + tid];
        v_sh[tid] = vw[n0 + tid];
    }

    // cp.async mapping: 8 x 16B segments per 128B row
    const int crow = tid >> 3;          // 0..63
    const int cseg = (tid & 7) * 8;     // half offset within row

    #pragma unroll
    for (int s = 0; s < STAGES; s++) {
        const int kf = s * BKH;
        const uint32_t stb = sb + s * STAGE_HALFS * 2;
        #pragma unroll
        for (int r = 0; r < 2; r++) {    // A: 128 rows
            int row = crow + r * 64;
            cp16(stb + (row * ROWH + cseg) * 2, Abase + (size_t)row * DIM + kf + cseg);
        }
        #pragma unroll
        for (int r = 0; r < 4; r++) {    // B: 256 rows
            int row = crow + r * 64;
            cp16(stb + (A_HALFS + row * ROWH + cseg) * 2,
                 Bbase + (size_t)row * DIM + kf + cseg);
        }
        CP_COMMIT();
    }

    // ldmatrix lane address components
    const int a_row = (lane & 7) + ((lane >> 3) & 1) * 8;   // 0..15
    const int a_col = ((lane >> 4) & 1) * 8;                // 0 | 8
    const int b_row = (lane & 7) + ((lane >> 4) & 1) * 8;
    const int b_col = ((lane >> 3) & 1) * 8;

    float acc[2][8][4];
    #pragma unroll
    for (int i = 0; i < 2; i++)
        #pragma unroll
        for (int j = 0; j < 8; j++)
            #pragma unroll
            for (int r = 0; r < 4; r++) acc[i][j][r] = 0.f;

    for (int kc = 0; kc < NCHUNK; kc++) {
        const int st = kc % STAGES;
        CP_WAIT(STAGES - 1);
        __syncthreads();

        const uint32_t stb = sb + st * STAGE_HALFS * 2;
        const uint32_t aoff = stb + ((wm * 32 + a_row) * ROWH + a_col) * 2;
        const uint32_t boff = stb + (A_HALFS + (wn * 64 + b_row) * ROWH + b_col) * 2;

        #pragma unroll
        for (int ks = 0; ks < 4; ks++) {
            const int kb = ks * 16;
            uint32_t af[2][4], bq[4][4];
            #pragma unroll
            for (int p = 0; p < 4; p++)
                ldm_x4(bq[p], boff + (p * 16 * ROWH + kb) * 2);
            #pragma unroll
            for (int i = 0; i < 2; i++)
                ldm_x4(af[i], aoff + (i * 16 * ROWH + kb) * 2);
            #pragma unroll
            for (int i = 0; i < 2; i++)
                #pragma unroll
                for (int j = 0; j < 8; j++)
                    mma_f16(acc[i][j], af[i], &bq[j >> 1][(j & 1) * 2]);
        }
        __syncthreads();

        const int kn = kc + STAGES;
        if (kn < NCHUNK) {
            const int kf = kn * BKH;
            const uint32_t stw = sb + st * STAGE_HALFS * 2;
            #pragma unroll
            for (int r = 0; r < 2; r++) {
                int row = crow + r * 64;
                cp16(stw + (row * ROWH + cseg) * 2, Abase + (size_t)row * DIM + kf + cseg);
            }
            #pragma unroll
            for (int r = 0; r < 4; r++) {
                int row = crow + r * 64;
                cp16(stw + (A_HALFS + row * ROWH + cseg) * 2,
                     Bbase + (size_t)row * DIM + kf + cseg);
            }
        }
        CP_COMMIT();
    }

    // Fused epilogue: reduce 256-wide d-chunk through tanh * v
    #pragma unroll
    for (int i = 0; i < 2; i++) {
        float slo = 0.f, shi = 0.f;
        #pragma unroll
        for (int j = 0; j < 8; j++) {
            const int c = wn * 64 + j * 8 + gc * 2;
            const float v0 = v_sh[c], v1 = v_sh[c + 1];
            const float q0 = q_sh[c], q1 = q_sh[c + 1];
            float x0 = q0 + acc[i][j][0], x1 = q1 + acc[i][j][1];
            float x2 = q0 + acc[i][j][2], x3 = q1 + acc[i][j][3];
            slo += v0 * (1.f - 2.f / (__expf(2.f * x0) + 1.f))
                 + v1 * (1.f - 2.f / (__expf(2.f * x1) + 1.f));
            shi += v0 * (1.f - 2.f / (__expf(2.f * x2) + 1.f))
                 + v1 * (1.f - 2.f / (__expf(2.f * x3) + 1.f));
        }
        slo += __shfl_xor_sync(0xffffffffu, slo, 1);
        slo += __shfl_xor_sync(0xffffffffu, slo, 2);
        shi += __shfl_xor_sync(0xffffffffu, shi, 1);
        shi += __shfl_xor_sync(0xffffffffu, shi, 2);
        if (gc == 0) {
            const int r = l0 + wm * 32 + i * 16 + gr;
            atomicAdd(&g_scores[(size_t)b * SEQ + r], slo);
            atomicAdd(&g_scores[(size_t)b * SEQ + r + 8], shi);
        }
    }
}

// ---------------------------------------------------------------------------
// Kernel 3: softmax over L per batch; zero-inits the context region of out.
// ---------------------------------------------------------------------------
__global__ void softmax_kernel(float* __restrict__ out) {
    __shared__ float sm[SEQ];
    __shared__ float red[256];
    const int b = blockIdx.x, tid = threadIdx.x;

    for (int d = tid; d < DIM; d += 256) out[b * DIM + d] = 0.f;

    float m = -1e30f;
    for (int l = tid; l < SEQ; l += 256) {
        float s = g_scores[b * SEQ + l];
        sm[l] = s;
        m = fmaxf(m, s);
    }
    red[tid] = m;
    __syncthreads();
    for (int o = 128; o; o >>= 1) {
        if (tid < o) red[tid] = fmaxf(red[tid], red[tid + o]);
        __syncthreads();
    }
    m = red[0];
    __syncthreads();

    float sum = 0.f;
    for (int l = tid; l < SEQ; l += 256) {
        float e = __expf(sm[l] - m);
        sm[l] = e;
        sum += e;
    }
    red[tid] = sum;
    __syncthreads();
    for (int o = 128; o; o >>= 1) {
        if (tid < o) red[tid] += red[tid + o];
        __syncthreads();
    }
    const float inv = 1.f / red[0];

    float* attn = out + BATCH * DIM;
    for (int l = tid; l < SEQ; l += 256) attn[b * SEQ + l] = sm[l] * inv;
}

// ---------------------------------------------------------------------------
// Kernel 4: context[b,d] += sum_{l in chunk} attn[b,l] * enc_h[b,l,d]
// fp16 enc (halved DRAM traffic), fp32 accumulate + atomicAdd.
// Grid (BATCH, 16): 128 L-rows per block.
// ---------------------------------------------------------------------------
__global__ void context_kernel(float* __restrict__ out) {
    __shared__ float attn_sm[128];
    const int b = blockIdx.x, ch = blockIdx.y, tid = threadIdx.x;
    const int lbase = ch * 128;
    if (tid < 128) attn_sm[tid] = out[BATCH * DIM + (size_t)b * SEQ + lbase + tid];
    __syncthreads();

    float acc0 = 0.f, acc1 = 0.f, acc2 = 0.f, acc3 = 0.f;
    const __half* ep = g_enc_h + ((size_t)b * SEQ + lbase) * DIM + tid * 4;
    #pragma unroll 8
    for (int l = 0; l < 128; ++l) {
        float a = attn_sm[l];
        uint2 raw = *(const uint2*)(ep + (size_t)l * DIM);
        __half2 h0 = *(__half2*)&raw.x, h1 = *(__half2*)&raw.y;
        float2 f0 = __half22float2(h0), f1 = __half22float2(h1);
        acc0 += a * f0.x; acc1 += a * f0.y;
        acc2 += a * f1.x; acc3 += a * f1.y;
    }
    float* dst = out + b * DIM + tid * 4;
    atomicAdd(dst + 0, acc0);
    atomicAdd(dst + 1, acc1);
    atomicAdd(dst + 2, acc2);
    atomicAdd(dst + 3, acc3);
}

// ---------------------------------------------------------------------------
extern "C" void kernel_launch(void* const* d_in, const int* in_sizes, int n_in,
                              void* d_out, int out_size) {
    const float* dh  = (const float*)d_in[0];   // [32,1,1024]
    const float* enc = (const float*)d_in[1];   // [32,2048,1024]
    const float* Ww  = (const float*)d_in[2];   // [1024,1024]
    const float* Wb  = (const float*)d_in[3];   // [1024]
    const float* Uw  = (const float*)d_in[4];   // [1024,1024]
    const float* Ub  = (const float*)d_in[5];   // [1024]
    const float* vw  = (const float*)d_in[6];   // [1,1024]
    float* out = (float*)d_out;                 // [32768 context | 65536 attn]

    (void)in_sizes; (void)n_in; (void)out_size;

    static bool attr_set = false;
    if (!attr_set) {
        cudaFuncSetAttribute(score_kernel,
                             cudaFuncAttributeMaxDynamicSharedMemorySize, SMEM_BYTES);
        attr_set = true;
    }

    const size_t nOps = ((size_t)BATCH * SEQ * DIM + (size_t)DIM * DIM) / 8;
    convert_kernel<<<(unsigned)((nOps + 255) / 256), 256>>>(enc, Uw);

    qproj_kernel<<<(BATCH * DIM * 32 + 255) / 256, 256>>>(dh, Ww, Wb, Ub);

    dim3 sgrid(DIM / BN, SEQ / BM, BATCH);   // (4? no: 1024/256=4 ... (4,16,32))
    score_kernel<<<sgrid, 512, SMEM_BYTES>>>(vw);

    softmax_kernel<<<BATCH, 256>>>(out);

    dim3 cgrid(BATCH, 16);
    context_kernel<<<cgrid, 256>>>(out);
}

// round 7
// speedup vs baseline: 7.3052x; 1.0197x over previous
#include <cuda_runtime.h>
#include <cuda_fp16.h>
#include <math.h>
#include <stdint.h>

#define BATCH 32
#define SEQ   2048
#define DIM   1024

#define BM 128
#define BN 256
#define BKH 64                      // k halfs per chunk (128 B)
#define KCHUNKS (DIM / BKH)         // 16 chunks per block (FULL K — no split)
#define STAGES 3
#define ROWH 72                     // halfs per smem row (144 B stride, LDSM conflict-free)
#define A_HALFS (BM * ROWH)         // 9216
#define STAGE_HALFS ((BM + BN) * ROWH)   // 27648
#define SMEM_BYTES (STAGES * STAGE_HALFS * 2 + 2 * BN * 4)

// Scratch (static __device__ — no allocation inside kernel_launch)
__device__ float  g_q[BATCH * DIM];
__device__ float  g_scores[BATCH * SEQ];
__device__ __half g_enc_h[(size_t)BATCH * SEQ * DIM];   // fp16 copy of enc
__device__ __half g_U_h[DIM * DIM];                     // fp16 copy of Uw

__device__ __forceinline__ uint32_t smem_u32(const void* p) {
    uint32_t a;
    asm("{ .reg .u64 t; cvta.to.shared.u64 t, %1; cvt.u32.u64 %0, t; }"
        : "=r"(a) : "l"(p));
    return a;
}

__device__ __forceinline__ void cp16(uint32_t dst, const void* src) {
    asm volatile("cp.async.cg.shared.global [%0], [%1], 16;"
                 :: "r"(dst), "l"(src) : "memory");
}
#define CP_COMMIT() asm volatile("cp.async.commit_group;" ::: "memory")
#define CP_WAIT(n)  asm volatile("cp.async.wait_group %0;" :: "n"(n) : "memory")

__device__ __forceinline__ void ldm_x4(uint32_t r[4], uint32_t addr) {
    asm volatile("ldmatrix.sync.aligned.m8n8.x4.shared.b16 {%0,%1,%2,%3}, [%4];"
                 : "=r"(r[0]), "=r"(r[1]), "=r"(r[2]), "=r"(r[3]) : "r"(addr));
}

__device__ __forceinline__ void mma_f16(float c[4], const uint32_t a[4], const uint32_t b[2]) {
    asm volatile(
        "mma.sync.aligned.m16n8k16.row.col.f32.f16.f16.f32 "
        "{%0,%1,%2,%3}, {%4,%5,%6,%7}, {%8,%9}, {%0,%1,%2,%3};"
        : "+f"(c[0]), "+f"(c[1]), "+f"(c[2]), "+f"(c[3])
        : "r"(a[0]), "r"(a[1]), "r"(a[2]), "r"(a[3]), "r"(b[0]), "r"(b[1]));
}

// ---------------------------------------------------------------------------
// Kernel 0 (merged prep): fp32->fp16 convert of enc & Uw, q' projection, and
// zeroing of g_scores, all in one launch.
// ---------------------------------------------------------------------------
#define NENC8  ((size_t)BATCH * SEQ * DIM / 8)          // 8388608
#define NU8    ((size_t)DIM * DIM / 8)                  // 131072
#define NCONV_BLOCKS ((unsigned)((NENC8 + NU8 + 255) / 256))   // 33280
#define NQP_BLOCKS   (BATCH * DIM / 8)                  // 4096 (8 warps/block)

__global__ void prep_kernel(const float* __restrict__ enc,
                            const float* __restrict__ Uw,
                            const float* __restrict__ dh,
                            const float* __restrict__ Ww,
                            const float* __restrict__ Wb,
                            const float* __restrict__ Ub) {
    if (blockIdx.x < NCONV_BLOCKS) {
        size_t i = (size_t)blockIdx.x * 256 + threadIdx.x;
        const float4* src;
        uint4* dst;
        size_t k;
        if (i < NENC8)            { src = (const float4*)enc; dst = (uint4*)g_enc_h; k = i; }
        else if (i < NENC8 + NU8) { src = (const float4*)Uw;  dst = (uint4*)g_U_h;   k = i - NENC8; }
        else return;
        float4 f0 = src[k * 2], f1 = src[k * 2 + 1];
        __half2 h[4];
        h[0] = __floats2half2_rn(f0.x, f0.y);
        h[1] = __floats2half2_rn(f0.z, f0.w);
        h[2] = __floats2half2_rn(f1.x, f1.y);
        h[3] = __floats2half2_rn(f1.z, f1.w);
        dst[k] = *(uint4*)h;
        return;
    }
    // qproj part
    int qgid = (int)(blockIdx.x - NCONV_BLOCKS) * 256 + threadIdx.x;
    if (qgid < BATCH * SEQ) g_scores[qgid] = 0.f;

    int warp = qgid >> 5;
    int lane = threadIdx.x & 31;
    if (warp >= BATCH * DIM) return;
    int b = warp / DIM, d = warp % DIM;
    const float* x = dh + b * DIM;
    const float* w = Ww + (size_t)d * DIM;
    float s = 0.f;
    #pragma unroll 4
    for (int e = lane; e < DIM; e += 32) s += x[e] * w[e];
    #pragma unroll
    for (int o = 16; o; o >>= 1) s += __shfl_xor_sync(0xffffffffu, s, o);
    if (lane == 0) g_q[warp] = s + Wb[d] + Ub[d];
}

// ---------------------------------------------------------------------------
// Kernel 2 (dominant): fp16 mma m16n8k16, cp.async 3-stage single-sync
// multistage pipeline, ldmatrix frags. Tile 128(l) x 256(d) x FULL K=1024;
// fused tanh*v epilogue; atomic score partials.
// Grid (4, 16, 32), 512 threads = 16 warps (4m x 4n), warp tile 32x64.
// ---------------------------------------------------------------------------
__global__ __launch_bounds__(512, 1)
void score_kernel(const float* __restrict__ vw) {
    extern __shared__ char smc[];
    const uint32_t sb = smem_u32(smc);

    const int tid  = threadIdx.x;
    const int wid  = tid >> 5;
    const int lane = tid & 31;
    const int wm   = wid & 3;
    const int wn   = wid >> 2;
    const int gr   = lane >> 2;
    const int gc   = lane & 3;

    const int n0 = blockIdx.x * BN;
    const int l0 = blockIdx.y * BM;
    const int b  = blockIdx.z;

    const __half* Abase = g_enc_h + ((size_t)b * SEQ + l0) * DIM;
    const __half* Bbase = g_U_h + (size_t)n0 * DIM;

    float* q_sh = (float*)(smc + STAGES * STAGE_HALFS * 2);
    float* v_sh = q_sh + BN;
    if (tid < BN) {
        q_sh[tid] = g_q[b * DIM + n0 + tid];
        v_sh[tid] = vw[n0 + tid];
    }

    // cp.async mapping: 8 x 16B segments per 128B chunk-row
    const int crow = tid >> 3;          // 0..63
    const int cseg = (tid & 7) * 8;     // half offset within row

    // prologue: fill stages 0 and 1
    #pragma unroll
    for (int s = 0; s < STAGES - 1; s++) {
        const int kf = s * BKH;
        const uint32_t stb = sb + s * STAGE_HALFS * 2;
        #pragma unroll
        for (int r = 0; r < 2; r++) {
            int row = crow + r * 64;
            cp16(stb + (row * ROWH + cseg) * 2, Abase + (size_t)row * DIM + kf + cseg);
        }
        #pragma unroll
        for (int r = 0; r < 4; r++) {
            int row = crow + r * 64;
            cp16(stb + (A_HALFS + row * ROWH + cseg) * 2,
                 Bbase + (size_t)row * DIM + kf + cseg);
        }
        CP_COMMIT();
    }

    // ldmatrix lane address components
    const int a_row = (lane & 7) + ((lane >> 3) & 1) * 8;
    const int a_col = ((lane >> 4) & 1) * 8;
    const int b_row = (lane & 7) + ((lane >> 4) & 1) * 8;
    const int b_col = ((lane >> 3) & 1) * 8;

    float acc[2][8][4];
    #pragma unroll
    for (int i = 0; i < 2; i++)
        #pragma unroll
        for (int j = 0; j < 8; j++)
            #pragma unroll
            for (int r = 0; r < 4; r++) acc[i][j][r] = 0.f;

    for (int kc = 0; kc < KCHUNKS; kc++) {
        CP_WAIT(1);
        __syncthreads();

        // refill stage (kc+2)%3 with chunk kc+2 (its prior contents were
        // consumed at iter kc-1; the sync above fences all warps past it)
        const int kn = kc + STAGES - 1;
        if (kn < KCHUNKS) {
            const int st_w = kn % STAGES;
            const int kf = kn * BKH;
            const uint32_t stw = sb + st_w * STAGE_HALFS * 2;
            #pragma unroll
            for (int r = 0; r < 2; r++) {
                int row = crow + r * 64;
                cp16(stw + (row * ROWH + cseg) * 2, Abase + (size_t)row * DIM + kf + cseg);
            }
            #pragma unroll
            for (int r = 0; r < 4; r++) {
                int row = crow + r * 64;
                cp16(stw + (A_HALFS + row * ROWH + cseg) * 2,
                     Bbase + (size_t)row * DIM + kf + cseg);
            }
        }
        CP_COMMIT();

        const uint32_t stb = sb + (kc % STAGES) * STAGE_HALFS * 2;
        const uint32_t aoff = stb + ((wm * 32 + a_row) * ROWH + a_col) * 2;
        const uint32_t boff = stb + (A_HALFS + (wn * 64 + b_row) * ROWH + b_col) * 2;

        #pragma unroll
        for (int ks = 0; ks < 4; ks++) {
            const int kb = ks * 16;
            uint32_t af[2][4], bq[4][4];
            #pragma unroll
            for (int p = 0; p < 4; p++)
                ldm_x4(bq[p], boff + (p * 16 * ROWH + kb) * 2);
            #pragma unroll
            for (int i = 0; i < 2; i++)
                ldm_x4(af[i], aoff + (i * 16 * ROWH + kb) * 2);
            #pragma unroll
            for (int i = 0; i < 2; i++)
                #pragma unroll
                for (int j = 0; j < 8; j++)
                    mma_f16(acc[i][j], af[i], &bq[j >> 1][(j & 1) * 2]);
        }
    }

    // Fused epilogue: reduce 256-wide d-chunk through tanh * v
    #pragma unroll
    for (int i = 0; i < 2; i++) {
        float slo = 0.f, shi = 0.f;
        #pragma unroll
        for (int j = 0; j < 8; j++) {
            const int c = wn * 64 + j * 8 + gc * 2;
            const float v0 = v_sh[c], v1 = v_sh[c + 1];
            const float q0 = q_sh[c], q1 = q_sh[c + 1];
            float x0 = q0 + acc[i][j][0], x1 = q1 + acc[i][j][1];
            float x2 = q0 + acc[i][j][2], x3 = q1 + acc[i][j][3];
            slo += v0 * (1.f - 2.f / (__expf(2.f * x0) + 1.f))
                 + v1 * (1.f - 2.f / (__expf(2.f * x1) + 1.f));
            shi += v0 * (1.f - 2.f / (__expf(2.f * x2) + 1.f))
                 + v1 * (1.f - 2.f / (__expf(2.f * x3) + 1.f));
        }
        slo += __shfl_xor_sync(0xffffffffu, slo, 1);
        slo += __shfl_xor_sync(0xffffffffu, slo, 2);
        shi += __shfl_xor_sync(0xffffffffu, shi, 1);
        shi += __shfl_xor_sync(0xffffffffu, shi, 2);
        if (gc == 0) {
            const int r = l0 + wm * 32 + i * 16 + gr;
            atomicAdd(&g_scores[(size_t)b * SEQ + r], slo);
            atomicAdd(&g_scores[(size_t)b * SEQ + r + 8], shi);
        }
    }
}

// ---------------------------------------------------------------------------
// Kernel 3: softmax over L per batch; zero-inits the context region of out.
// ---------------------------------------------------------------------------
__global__ void softmax_kernel(float* __restrict__ out) {
    __shared__ float sm[SEQ];
    __shared__ float red[256];
    const int b = blockIdx.x, tid = threadIdx.x;

    for (int d = tid; d < DIM; d += 256) out[b * DIM + d] = 0.f;

    float m = -1e30f;
    for (int l = tid; l < SEQ; l += 256) {
        float s = g_scores[b * SEQ + l];
        sm[l] = s;
        m = fmaxf(m, s);
    }
    red[tid] = m;
    __syncthreads();
    for (int o = 128; o; o >>= 1) {
        if (tid < o) red[tid] = fmaxf(red[tid], red[tid + o]);
        __syncthreads();
    }
    m = red[0];
    __syncthreads();

    float sum = 0.f;
    for (int l = tid; l < SEQ; l += 256) {
        float e = __expf(sm[l] - m);
        sm[l] = e;
        sum += e;
    }
    red[tid] = sum;
    __syncthreads();
    for (int o = 128; o; o >>= 1) {
        if (tid < o) red[tid] += red[tid + o];
        __syncthreads();
    }
    const float inv = 1.f / red[0];

    float* attn = out + BATCH * DIM;
    for (int l = tid; l < SEQ; l += 256) attn[b * SEQ + l] = sm[l] * inv;
}

// ---------------------------------------------------------------------------
// Kernel 4: context[b,d] += sum_{l in chunk} attn[b,l] * enc_h[b,l,d]
// fp16 enc, fp32 accumulate + atomicAdd. Grid (BATCH, 32): 64 rows/block.
// ---------------------------------------------------------------------------
__global__ void context_kernel(float* __restrict__ out) {
    __shared__ float attn_sm[64];
    const int b = blockIdx.x, ch = blockIdx.y, tid = threadIdx.x;
    const int lbase = ch * 64;
    if (tid < 64) attn_sm[tid] = out[BATCH * DIM + (size_t)b * SEQ + lbase + tid];
    __syncthreads();

    float acc0 = 0.f, acc1 = 0.f, acc2 = 0.f, acc3 = 0.f;
    const __half* ep = g_enc_h + ((size_t)b * SEQ + lbase) * DIM + tid * 4;
    #pragma unroll 8
    for (int l = 0; l < 64; ++l) {
        float a = attn_sm[l];
        uint2 raw = *(const uint2*)(ep + (size_t)l * DIM);
        __half2 h0 = *(__half2*)&raw.x, h1 = *(__half2*)&raw.y;
        float2 f0 = __half22float2(h0), f1 = __half22float2(h1);
        acc0 += a * f0.x; acc1 += a * f0.y;
        acc2 += a * f1.x; acc3 += a * f1.y;
    }
    float* dst = out + b * DIM + tid * 4;
    atomicAdd(dst + 0, acc0);
    atomicAdd(dst + 1, acc1);
    atomicAdd(dst + 2, acc2);
    atomicAdd(dst + 3, acc3);
}

// ---------------------------------------------------------------------------
extern "C" void kernel_launch(void* const* d_in, const int* in_sizes, int n_in,
                              void* d_out, int out_size) {
    const float* dh  = (const float*)d_in[0];   // [32,1,1024]
    const float* enc = (const float*)d_in[1];   // [32,2048,1024]
    const float* Ww  = (const float*)d_in[2];   // [1024,1024]
    const float* Wb  = (const float*)d_in[3];   // [1024]
    const float* Uw  = (const float*)d_in[4];   // [1024,1024]
    const float* Ub  = (const float*)d_in[5];   // [1024]
    const float* vw  = (const float*)d_in[6];   // [1,1024]
    float* out = (float*)d_out;                 // [32768 context | 65536 attn]

    (void)in_sizes; (void)n_in; (void)out_size;

    static bool attr_set = false;
    if (!attr_set) {
        cudaFuncSetAttribute(score_kernel,
                             cudaFuncAttributeMaxDynamicSharedMemorySize, SMEM_BYTES);
        attr_set = true;
    }

    prep_kernel<<<NCONV_BLOCKS + NQP_BLOCKS, 256>>>(enc, Uw, dh, Ww, Wb, Ub);

    dim3 sgrid(DIM / BN, SEQ / BM, BATCH);   // (4, 16, 32) — each block owns full K
    score_kernel<<<sgrid, 512, SMEM_BYTES>>>(vw);

    softmax_kernel<<<BATCH, 256>>>(out);

    dim3 cgrid(BATCH, 32);
    context_kernel<<<cgrid, 256>>>(out);
}